// round 16
// baseline (speedup 1.0000x reference)
#include <cuda_runtime.h>
#include <math.h>

#define NTOK 1024
#define DK   128
#define DAPP 2048
#define DG   128

// Scratch (no cudaMalloc allowed)
__device__ float g_q [NTOK*DK];
__device__ float g_k [NTOK*DK];
__device__ float g_vt[DK*NTOK];     // V transposed: vt[d][m]
__device__ float g_sd[NTOK*NTOK];   // scaled dot QK^T/sqrt(dk)
__device__ float g_p [NTOK*NTOK];   // gbias, then softmax probabilities (in place)
__device__ int   g_qkv_done;        // QKV completion counter (reset each launch)

#define QKV_ROLES 768

// ---------------------------------------------------------------------------
// Init: bias-seed q,k,vt (split-K GEMMs accumulate on top), zero final out,
// reset the QKV completion counter (graph replays re-run this every launch).
// ---------------------------------------------------------------------------
__global__ void init_kernel(float* __restrict__ out,
                            const float* __restrict__ qb,
                            const float* __restrict__ kb,
                            const float* __restrict__ vb)
{
    int idx = blockIdx.x * blockDim.x + threadIdx.x;
    if (idx == 0) g_qkv_done = 0;
    if (idx < NTOK * DK) {
        int d = idx & (DK - 1);
        g_q[idx]  = qb[d];
        g_k[idx]  = kb[d];
        g_vt[idx] = vb[idx >> 10];   // vt[d][m], d = idx/1024
        out[idx]  = 0.0f;
    }
}

// ---------------------------------------------------------------------------
// GEMM body: BM=32, BN=128, BK=16, 256 threads, 4x4 micro-tile (~45 regs).
// C[m][n] (+)= alpha * sum_k A[m][k] * B[n][k]
// ---------------------------------------------------------------------------
template<int ATOMIC>
__device__ __forceinline__
void gemm32x128_body(const float* __restrict__ A, int lda,
                     const float* __restrict__ B, int ldb,
                     float* __restrict__ C, int ldc,
                     int m0, int n0, int kbeg, int kend,
                     float alpha, int transc)
{
    __shared__ float As[16][32];    // [k][m]
    __shared__ float Bs[16][128];   // [k][n]

    const int tid = threadIdx.x;
    const int rg  = tid >> 5;   // 0..7  -> rows m0 + rg*4 + i
    const int cg  = tid & 31;   // 0..31 -> cols n0 + cg*4 + j

    float acc[4][4];
#pragma unroll
    for (int i = 0; i < 4; i++)
#pragma unroll
        for (int j = 0; j < 4; j++) acc[i][j] = 0.0f;

    for (int kt = kbeg; kt < kend; kt += 16) {
        if (tid < 128) {   // A tile 32x16 (128 float4)
            int row = tid >> 2, c4 = tid & 3;
            float4 v = *(const float4*)(A + (size_t)(m0 + row) * lda + kt + c4 * 4);
            As[c4*4+0][row] = v.x; As[c4*4+1][row] = v.y;
            As[c4*4+2][row] = v.z; As[c4*4+3][row] = v.w;
        }
#pragma unroll
        for (int i = 0; i < 2; i++) {   // B tile 128x16 (512 float4)
            int fid = tid * 2 + i;
            int row = fid >> 2, c4 = fid & 3;
            float4 v = *(const float4*)(B + (size_t)(n0 + row) * ldb + kt + c4 * 4);
            Bs[c4*4+0][row] = v.x; Bs[c4*4+1][row] = v.y;
            Bs[c4*4+2][row] = v.z; Bs[c4*4+3][row] = v.w;
        }
        __syncthreads();

#pragma unroll
        for (int kk = 0; kk < 16; kk++) {
            float a[4], b[4];
            *(float4*)&a[0] = *(const float4*)&As[kk][rg * 4];
            *(float4*)&b[0] = *(const float4*)&Bs[kk][cg * 4];
#pragma unroll
            for (int i = 0; i < 4; i++)
#pragma unroll
                for (int j = 0; j < 4; j++)
                    acc[i][j] += a[i] * b[j];
        }
        __syncthreads();
    }

#pragma unroll
    for (int i = 0; i < 4; i++) {
#pragma unroll
        for (int j = 0; j < 4; j++) {
            int m = m0 + rg * 4 + i;
            int n = n0 + cg * 4 + j;
            float v = alpha * acc[i][j];
            int idx = transc ? (n * ldc + m) : (m * ldc + n);
            if (ATOMIC) atomicAdd(&C[idx], v);
            else        C[idx] = v;
        }
    }
}

// ---------------------------------------------------------------------------
// gbias block role: one warp per 512B row, wg in registers, shuffle reduce.
// Each role covers 8 warps x 64 rows = 512 rows of pos.
// ---------------------------------------------------------------------------
__device__ __forceinline__
void gbias_body(const float* __restrict__ pos,
                const float* __restrict__ wg,
                const float* __restrict__ wgb,
                int blk)
{
    const int lane  = threadIdx.x & 31;
    const int gwarp = blk * 8 + (threadIdx.x >> 5);

    const float4 w  = ((const float4*)wg)[lane];
    const float  gb = wgb[0];

    const size_t row0 = (size_t)gwarp * 64;
    const float4* base = (const float4*)pos;   // row r at base + r*32 + lane

#pragma unroll 2
    for (int r = 0; r < 64; r += 4) {
        size_t rr = row0 + r;
        float4 x0 = __ldcs(base + (rr + 0) * 32 + lane);
        float4 x1 = __ldcs(base + (rr + 1) * 32 + lane);
        float4 x2 = __ldcs(base + (rr + 2) * 32 + lane);
        float4 x3 = __ldcs(base + (rr + 3) * 32 + lane);

        float s0 = x0.x*w.x + x0.y*w.y + x0.z*w.z + x0.w*w.w;
        float s1 = x1.x*w.x + x1.y*w.y + x1.z*w.z + x1.w*w.w;
        float s2 = x2.x*w.x + x2.y*w.y + x2.z*w.z + x2.w*w.w;
        float s3 = x3.x*w.x + x3.y*w.y + x3.z*w.z + x3.w*w.w;

#pragma unroll
        for (int o = 16; o > 0; o >>= 1) {
            s0 += __shfl_xor_sync(0xFFFFFFFFu, s0, o);
            s1 += __shfl_xor_sync(0xFFFFFFFFu, s1, o);
            s2 += __shfl_xor_sync(0xFFFFFFFFu, s2, o);
            s3 += __shfl_xor_sync(0xFFFFFFFFu, s3, o);
        }

        if (lane < 4) {
            float v = (lane == 0) ? s0 : (lane == 1) ? s1 : (lane == 2) ? s2 : s3;
            g_p[rr + lane] = fmaxf(v + gb, 0.0f);
        }
    }
}

// ---------------------------------------------------------------------------
// Single fused kernel. Block-role layout (ascending bid dispatch):
//   [0, 768)       QKV GEMM roles: 32 m-tiles x 3 heads x 8 split-K,
//                  kchunk=256, atomic onto bias-seeded q/k/vt. Signal counter.
//   [768, 2816)    gbias roles: full unbroken 512 MB stream (2048 roles).
//   [2816, 3072)   sd roles: spin on counter==768 (all QKV blocks were
//                  dispatched before any sd block -> no deadlock), then
//                  sd = q.k^T/sqrt(128): 32 m-tiles x 8 n-tiles, direct store.
// ---------------------------------------------------------------------------
__global__ __launch_bounds__(256)
void fused_main(const float* __restrict__ pos,
                const float* __restrict__ wg,
                const float* __restrict__ wgb,
                const float* __restrict__ app,
                const float* __restrict__ wq,
                const float* __restrict__ wk,
                const float* __restrict__ wv)
{
    const int g = blockIdx.x;

    if (g < QKV_ROLES) {
        int mt   = g & 31;                   // 0..31
        int rest = g >> 5;                   // 0..23
        int head = rest % 3;
        int kz   = rest / 3;                 // 0..7
        const float* B;
        float* C;
        int transc = 0, ldc = DK;
        if (head == 0)      { B = wq; C = g_q; }
        else if (head == 1) { B = wk; C = g_k; }
        else                { B = wv; C = g_vt; transc = 1; ldc = NTOK; }
        gemm32x128_body<1>(app, DAPP, B, DAPP, C, ldc,
                           mt * 32, 0, kz * 256, kz * 256 + 256, 1.0f, transc);
        // release: make atomics visible, then signal completion
        __syncthreads();
        if (threadIdx.x == 0) {
            __threadfence();
            atomicAdd(&g_qkv_done, 1);
        }
    } else if (g < QKV_ROLES + 2048) {
        gbias_body(pos, wg, wgb, g - QKV_ROLES);
    } else {
        // sd role: wait for all QKV blocks (acquire), then compute
        if (threadIdx.x == 0) {
            while (atomicAdd(&g_qkv_done, 0) < QKV_ROLES)
                __nanosleep(200);
        }
        __syncthreads();
        __threadfence();
        int si = g - (QKV_ROLES + 2048);     // 0..255
        int mt = si & 31;
        int nt = si >> 5;                    // 0..7
        gemm32x128_body<0>(g_q, DK, g_k, DK, g_sd, NTOK,
                           mt * 32, nt * 128, 0, 128,
                           0.088388347648318447f, 0);
    }
}

// ---------------------------------------------------------------------------
// pv: out = P . V (V transposed), 32 m-tiles x 8 split-K (kchunk 128).
// ---------------------------------------------------------------------------
__global__ __launch_bounds__(256)
void pv_gemm(float* __restrict__ out)
{
    int mt = blockIdx.x & 31;
    int kz = blockIdx.x >> 5;     // 0..7
    gemm32x128_body<1>(g_p, NTOK, g_vt, NTOK, out, DK,
                       mt * 32, 0, kz * 128, kz * 128 + 128, 1.0f, 0);
}

// ---------------------------------------------------------------------------
// Row softmax over (sd + gbias), in place into g_p. One block per row,
// 256 threads x float4 = 1024 cols, values held in registers.
// ---------------------------------------------------------------------------
__global__ __launch_bounds__(256)
void softmax_rows()
{
    __shared__ float red[8];
    __shared__ float bcast;

    const int tid = threadIdx.x;
    const int m   = blockIdx.x;

    const float4* sd4 = (const float4*)(g_sd + (size_t)m * NTOK);
    float4*       p4  = (float4*)(g_p  + (size_t)m * NTOK);

    float4 a = sd4[tid];
    float4 b = p4[tid];
    float v0 = a.x + b.x, v1 = a.y + b.y, v2 = a.z + b.z, v3 = a.w + b.w;

    // ---- max ----
    float lm = fmaxf(fmaxf(v0, v1), fmaxf(v2, v3));
#pragma unroll
    for (int o = 16; o > 0; o >>= 1) lm = fmaxf(lm, __shfl_xor_sync(0xFFFFFFFFu, lm, o));
    if ((tid & 31) == 0) red[tid >> 5] = lm;
    __syncthreads();
    if (tid == 0) {
        float mm = red[0];
#pragma unroll
        for (int i = 1; i < 8; i++) mm = fmaxf(mm, red[i]);
        bcast = mm;
    }
    __syncthreads();
    const float rmax = bcast;
    __syncthreads();   // protect red[] reuse

    // ---- exp & sum ----
    float e0 = __expf(v0 - rmax), e1 = __expf(v1 - rmax);
    float e2 = __expf(v2 - rmax), e3 = __expf(v3 - rmax);
    float ls = (e0 + e1) + (e2 + e3);
#pragma unroll
    for (int o = 16; o > 0; o >>= 1) ls += __shfl_xor_sync(0xFFFFFFFFu, ls, o);
    if ((tid & 31) == 0) red[tid >> 5] = ls;
    __syncthreads();
    if (tid == 0) {
        float ss = red[0];
#pragma unroll
        for (int i = 1; i < 8; i++) ss += red[i];
        bcast = ss;
    }
    __syncthreads();
    const float inv = 1.0f / bcast;

    p4[tid] = make_float4(e0 * inv, e1 * inv, e2 * inv, e3 * inv);
}

// ---------------------------------------------------------------------------
extern "C" void kernel_launch(void* const* d_in, const int* in_sizes, int n_in,
                              void* d_out, int out_size)
{
    const float* app = (const float*)d_in[0];
    const float* pos = (const float*)d_in[1];
    const float* wqw = (const float*)d_in[2];
    const float* wqb = (const float*)d_in[3];
    const float* wkw = (const float*)d_in[4];
    const float* wkb = (const float*)d_in[5];
    const float* wvw = (const float*)d_in[6];
    const float* wvb = (const float*)d_in[7];
    const float* wgw = (const float*)d_in[8];
    const float* wgb = (const float*)d_in[9];
    float* out = (float*)d_out;

    // 1) bias seed + zero out + reset completion counter
    init_kernel<<<(NTOK*DK + 255) / 256, 256>>>(out, wqb, wkb, wvb);

    // 2) one fused kernel: QKV (first) + full gbias stream + sd (spin-wait last)
    fused_main<<<3072, 256>>>(pos, wgw, wgb, app, wqw, wkw, wvw);

    // 3) softmax(sd + gbias) -> P (in place in g_p)
    softmax_rows<<<NTOK, 256>>>();

    // 4) out = P . V (V transposed), split-K=8: 256 blocks
    pv_gemm<<<256, 256>>>(out);
}

// round 17
// speedup vs baseline: 1.3362x; 1.3362x over previous
#include <cuda_runtime.h>
#include <math.h>

#define NTOK 1024
#define DK   128
#define DAPP 2048
#define DG   128

// Scratch (no cudaMalloc allowed)
__device__ float g_q [NTOK*DK];
__device__ float g_k [NTOK*DK];
__device__ float g_vt[DK*NTOK];     // V transposed: vt[d][m]
__device__ float g_sd[NTOK*NTOK];   // scaled dot QK^T/sqrt(dk)
__device__ float g_p [NTOK*NTOK];   // gbias, then softmax probabilities (in place)

// ---------------------------------------------------------------------------
// Init: bias-seed q,k,vt (split-K GEMMs accumulate on top), zero final out.
// ---------------------------------------------------------------------------
__global__ void init_kernel(float* __restrict__ out,
                            const float* __restrict__ qb,
                            const float* __restrict__ kb,
                            const float* __restrict__ vb)
{
    int idx = blockIdx.x * blockDim.x + threadIdx.x;
    if (idx < NTOK * DK) {
        int d = idx & (DK - 1);
        g_q[idx]  = qb[d];
        g_k[idx]  = kb[d];
        g_vt[idx] = vb[idx >> 10];   // vt[d][m], d = idx/1024
        out[idx]  = 0.0f;
    }
}

// ---------------------------------------------------------------------------
// GEMM body: BM=32, BN=128, BK=16, 256 threads, 4x4 micro-tile (~45 regs).
// C[m][n] (+)= alpha * sum_k A[m][k] * B[n][k]
// As read is warp-broadcast; Bs read is phase-conflict-free (LDS.128).
// ---------------------------------------------------------------------------
template<int ATOMIC>
__device__ __forceinline__
void gemm256_body(const float* __restrict__ A, int lda,
                  const float* __restrict__ B, int ldb,
                  float* __restrict__ C, int ldc,
                  int m0, int n0, int kbeg, int kend,
                  float alpha, int transc)
{
    __shared__ float As[16][32];    // [k][m]
    __shared__ float Bs[16][128];   // [k][n]

    const int tid = threadIdx.x;
    const int rg  = tid >> 5;   // 0..7  -> rows m0 + rg*4 + i (same for warp)
    const int cg  = tid & 31;   // 0..31 -> cols n0 + cg*4 + j

    float acc[4][4];
#pragma unroll
    for (int i = 0; i < 4; i++)
#pragma unroll
        for (int j = 0; j < 4; j++) acc[i][j] = 0.0f;

    for (int kt = kbeg; kt < kend; kt += 16) {
        if (tid < 128) {   // A tile 32x16 (128 float4)
            int row = tid >> 2, c4 = tid & 3;
            float4 v = *(const float4*)(A + (size_t)(m0 + row) * lda + kt + c4 * 4);
            As[c4*4+0][row] = v.x; As[c4*4+1][row] = v.y;
            As[c4*4+2][row] = v.z; As[c4*4+3][row] = v.w;
        }
        // B tile 128x16 (512 float4, 2 per thread)
#pragma unroll
        for (int i = 0; i < 2; i++) {
            int fid = tid * 2 + i;
            int row = fid >> 2, c4 = fid & 3;
            float4 v = *(const float4*)(B + (size_t)(n0 + row) * ldb + kt + c4 * 4);
            Bs[c4*4+0][row] = v.x; Bs[c4*4+1][row] = v.y;
            Bs[c4*4+2][row] = v.z; Bs[c4*4+3][row] = v.w;
        }
        __syncthreads();

#pragma unroll
        for (int kk = 0; kk < 16; kk++) {
            float a[4], b[4];
            *(float4*)&a[0] = *(const float4*)&As[kk][rg * 4];
            *(float4*)&b[0] = *(const float4*)&Bs[kk][cg * 4];
#pragma unroll
            for (int i = 0; i < 4; i++)
#pragma unroll
                for (int j = 0; j < 4; j++)
                    acc[i][j] += a[i] * b[j];
        }
        __syncthreads();
    }

#pragma unroll
    for (int i = 0; i < 4; i++) {
#pragma unroll
        for (int j = 0; j < 4; j++) {
            int m = m0 + rg * 4 + i;
            int n = n0 + cg * 4 + j;
            float v = alpha * acc[i][j];
            int idx = transc ? (n * ldc + m) : (m * ldc + n);
            if (ATOMIC) atomicAdd(&C[idx], v);
            else        C[idx] = v;
        }
    }
}

// ---------------------------------------------------------------------------
// gbias block role: one warp per 512B row, wg in registers, shuffle reduce.
// Each block-role covers 8 warps x 64 rows = 512 rows of pos (rowbase offset).
// ---------------------------------------------------------------------------
__device__ __forceinline__
void gbias_body(const float* __restrict__ pos,
                const float* __restrict__ wg,
                const float* __restrict__ wgb,
                int blk, size_t rowbase)
{
    const int lane  = threadIdx.x & 31;
    const int gwarp = blk * 8 + (threadIdx.x >> 5);

    const float4 w  = ((const float4*)wg)[lane];
    const float  gb = wgb[0];

    const size_t row0 = rowbase + (size_t)gwarp * 64;
    const float4* base = (const float4*)pos;   // row r at base + r*32 + lane

#pragma unroll 2
    for (int r = 0; r < 64; r += 4) {
        size_t rr = row0 + r;
        float4 x0 = __ldcs(base + (rr + 0) * 32 + lane);
        float4 x1 = __ldcs(base + (rr + 1) * 32 + lane);
        float4 x2 = __ldcs(base + (rr + 2) * 32 + lane);
        float4 x3 = __ldcs(base + (rr + 3) * 32 + lane);

        float s0 = x0.x*w.x + x0.y*w.y + x0.z*w.z + x0.w*w.w;
        float s1 = x1.x*w.x + x1.y*w.y + x1.z*w.z + x1.w*w.w;
        float s2 = x2.x*w.x + x2.y*w.y + x2.z*w.z + x2.w*w.w;
        float s3 = x3.x*w.x + x3.y*w.y + x3.z*w.z + x3.w*w.w;

#pragma unroll
        for (int o = 16; o > 0; o >>= 1) {
            s0 += __shfl_xor_sync(0xFFFFFFFFu, s0, o);
            s1 += __shfl_xor_sync(0xFFFFFFFFu, s1, o);
            s2 += __shfl_xor_sync(0xFFFFFFFFu, s2, o);
            s3 += __shfl_xor_sync(0xFFFFFFFFu, s3, o);
        }

        if (lane < 4) {
            float v = (lane == 0) ? s0 : (lane == 1) ? s1 : (lane == 2) ? s2 : s3;
            g_p[rr + lane] = fmaxf(v + gb, 0.0f);
        }
    }
}

// ---------------------------------------------------------------------------
// Fused kernel A: gbias rows [0, 512K) (1024 roles) + QKV GEMM (768 roles).
// Grid 1792 = 256*7, interleave 4:3 via g%7. QKV: 32 m-tiles x 3 heads x
// 8 split-K, kchunk=256, atomic onto bias-seeded q/k/vt.
// ---------------------------------------------------------------------------
__global__ __launch_bounds__(256)
void fusedA(const float* __restrict__ pos,
            const float* __restrict__ wg,
            const float* __restrict__ wgb,
            const float* __restrict__ app,
            const float* __restrict__ wq,
            const float* __restrict__ wk,
            const float* __restrict__ wv)
{
    const int g  = blockIdx.x;
    const int gq = g / 7;
    const int r7 = g - gq * 7;
    if (r7 < 4) {
        gbias_body(pos, wg, wgb, gq * 4 + r7, 0);
    } else {
        int qi   = gq * 3 + (r7 - 4);        // 0..767
        int mt   = qi & 31;
        int rest = qi >> 5;                  // 0..23
        int head = rest % 3;
        int kz   = rest / 3;                 // 0..7
        const float* B;
        float* C;
        int transc = 0, ldc = DK;
        if (head == 0)      { B = wq; C = g_q; }
        else if (head == 1) { B = wk; C = g_k; }
        else                { B = wv; C = g_vt; transc = 1; ldc = NTOK; }
        gemm256_body<1>(app, DAPP, B, DAPP, C, ldc,
                        mt * 32, 0, kz * 256, kz * 256 + 256, 1.0f, transc);
    }
}

// ---------------------------------------------------------------------------
// Fused kernel B: gbias rows [512K, 1M) (1024 roles) + sd GEMM (256 roles).
// Grid 1280 = 256*5, interleave 4:1 via g%5. sd: 32 m-tiles x 8 n-tiles,
// K=128 full, direct store with alpha = 1/sqrt(128).
// ---------------------------------------------------------------------------
__global__ __launch_bounds__(256)
void fusedB(const float* __restrict__ pos,
            const float* __restrict__ wg,
            const float* __restrict__ wgb)
{
    const int g  = blockIdx.x;
    const int gq = g / 5;
    const int r5 = g - gq * 5;
    if (r5 < 4) {
        gbias_body(pos, wg, wgb, gq * 4 + r5, (size_t)512 * 1024);
    } else {
        int si = gq;               // 0..255
        int mt = si & 31;
        int nt = si >> 5;          // 0..7
        gemm256_body<0>(g_q, DK, g_k, DK, g_sd, NTOK,
                        mt * 32, nt * 128, 0, 128,
                        0.088388347648318447f, 0);
    }
}

// ---------------------------------------------------------------------------
// pv: out = P . V (V transposed), 32 m-tiles x 16 split-K (kchunk 64)
// = 512 blocks (was 256 @ split-K 8: occ 20.8%, 26.4us, latency-bound).
// ---------------------------------------------------------------------------
__global__ __launch_bounds__(256)
void pv_gemm(float* __restrict__ out)
{
    int mt = blockIdx.x & 31;
    int kz = blockIdx.x >> 5;     // 0..15
    gemm256_body<1>(g_p, NTOK, g_vt, NTOK, out, DK,
                    mt * 32, 0, kz * 64, kz * 64 + 64, 1.0f, 0);
}

// ---------------------------------------------------------------------------
// Row softmax over (sd + gbias), in place into g_p. One block per row,
// 256 threads x float4 = 1024 cols, values held in registers.
// ---------------------------------------------------------------------------
__global__ __launch_bounds__(256)
void softmax_rows()
{
    __shared__ float red[8];
    __shared__ float bcast;

    const int tid = threadIdx.x;
    const int m   = blockIdx.x;

    const float4* sd4 = (const float4*)(g_sd + (size_t)m * NTOK);
    float4*       p4  = (float4*)(g_p  + (size_t)m * NTOK);

    float4 a = sd4[tid];
    float4 b = p4[tid];
    float v0 = a.x + b.x, v1 = a.y + b.y, v2 = a.z + b.z, v3 = a.w + b.w;

    // ---- max ----
    float lm = fmaxf(fmaxf(v0, v1), fmaxf(v2, v3));
#pragma unroll
    for (int o = 16; o > 0; o >>= 1) lm = fmaxf(lm, __shfl_xor_sync(0xFFFFFFFFu, lm, o));
    if ((tid & 31) == 0) red[tid >> 5] = lm;
    __syncthreads();
    if (tid == 0) {
        float mm = red[0];
#pragma unroll
        for (int i = 1; i < 8; i++) mm = fmaxf(mm, red[i]);
        bcast = mm;
    }
    __syncthreads();
    const float rmax = bcast;
    __syncthreads();   // protect red[] reuse

    // ---- exp & sum ----
    float e0 = __expf(v0 - rmax), e1 = __expf(v1 - rmax);
    float e2 = __expf(v2 - rmax), e3 = __expf(v3 - rmax);
    float ls = (e0 + e1) + (e2 + e3);
#pragma unroll
    for (int o = 16; o > 0; o >>= 1) ls += __shfl_xor_sync(0xFFFFFFFFu, ls, o);
    if ((tid & 31) == 0) red[tid >> 5] = ls;
    __syncthreads();
    if (tid == 0) {
        float ss = red[0];
#pragma unroll
        for (int i = 1; i < 8; i++) ss += red[i];
        bcast = ss;
    }
    __syncthreads();
    const float inv = 1.0f / bcast;

    p4[tid] = make_float4(e0 * inv, e1 * inv, e2 * inv, e3 * inv);
}

// ---------------------------------------------------------------------------
extern "C" void kernel_launch(void* const* d_in, const int* in_sizes, int n_in,
                              void* d_out, int out_size)
{
    const float* app = (const float*)d_in[0];
    const float* pos = (const float*)d_in[1];
    const float* wqw = (const float*)d_in[2];
    const float* wqb = (const float*)d_in[3];
    const float* wkw = (const float*)d_in[4];
    const float* wkb = (const float*)d_in[5];
    const float* wvw = (const float*)d_in[6];
    const float* wvb = (const float*)d_in[7];
    const float* wgw = (const float*)d_in[8];
    const float* wgb = (const float*)d_in[9];
    float* out = (float*)d_out;

    // 1) bias seed + zero out
    init_kernel<<<(NTOK*DK + 255) / 256, 256>>>(out, wqb, wkb, wvb);

    // 2) fused: gbias half 1 (DRAM-bound) + QKV GEMM (hides in idle issue slots)
    fusedA<<<1792, 256>>>(pos, wgw, wgb, app, wqw, wkw, wvw);

    // 3) fused: gbias half 2 + sd = q.k^T / sqrt(128)
    fusedB<<<1280, 256>>>(pos, wgw, wgb);

    // 4) softmax(sd + gbias) -> P (in place in g_p)
    softmax_rows<<<NTOK, 256>>>();

    // 5) out = P . V (V transposed), split-K=16: 512 blocks
    pv_gemm<<<512, 256>>>(out);
}